// round 3
// baseline (speedup 1.0000x reference)
#include <cuda_runtime.h>
#include <cstdio>

#define N_NODES 50000
#define N_EDGES 800000
#define F_IN    128
#define HID     256

// ---------------- device scratch (static allocation only) ----------------
__device__ int   g_deg[N_NODES];
__device__ int   g_off[N_NODES + 1];
__device__ int   g_cur[N_NODES];
__device__ int   g_csr[N_EDGES];
__device__ float g_A1[(size_t)N_NODES * 256];   // [agg1_mean | x]        K=256
__device__ float g_h1[(size_t)N_NODES * 256];   // relu(layer1)
__device__ float g_A2[(size_t)N_NODES * 512];   // [agg2_mean | h1]       K=512
__device__ float g_B1[256 * 256];               // packed [K=256, O=256]
__device__ float g_B2[512 * 256];               // packed [K=512, O=256]

// ---------------- CSR build ----------------
__global__ void zero_deg_kernel() {
    int i = blockIdx.x * blockDim.x + threadIdx.x;
    if (i < N_NODES) g_deg[i] = 0;
}

__global__ void count_kernel(const int* __restrict__ dst) {
    int e = blockIdx.x * blockDim.x + threadIdx.x;
    if (e < N_EDGES) atomicAdd(&g_deg[dst[e]], 1);
}

// single-block hierarchical scan over degrees -> exclusive offsets (+ cursor copy)
__global__ void scan_kernel() {
    __shared__ int s[1024];
    int tid = threadIdx.x;
    int carry = 0;
    for (int base = 0; base < N_NODES; base += 1024) {
        int i = base + tid;
        int v = (i < N_NODES) ? g_deg[i] : 0;
        s[tid] = v;
        __syncthreads();
        #pragma unroll
        for (int off = 1; off < 1024; off <<= 1) {
            int t = (tid >= off) ? s[tid - off] : 0;
            __syncthreads();
            s[tid] += t;
            __syncthreads();
        }
        if (i < N_NODES) {
            int excl = carry + s[tid] - v;
            g_off[i] = excl;
            g_cur[i] = excl;
        }
        carry += s[1023];
        __syncthreads();
    }
    if (tid == 0) g_off[N_NODES] = carry;
}

__global__ void fill_kernel(const int* __restrict__ src, const int* __restrict__ dst) {
    int e = blockIdx.x * blockDim.x + threadIdx.x;
    if (e < N_EDGES) {
        int d = dst[e];
        int p = atomicAdd(&g_cur[d], 1);
        g_csr[p] = src[e];
    }
}

// ---------------- weight packing:  B[k][o] layout, concat of (Wl | Wr) along K ----------------
__global__ void pack1_kernel(const float* __restrict__ W1l, const float* __restrict__ W1r) {
    int idx = blockIdx.x * blockDim.x + threadIdx.x;
    if (idx >= 256 * 256) return;
    int k = idx / 256, o = idx % 256;
    g_B1[idx] = (k < 128) ? W1l[o * 128 + k] : W1r[o * 128 + (k - 128)];
}

__global__ void pack2_kernel(const float* __restrict__ W2l, const float* __restrict__ W2r) {
    int idx = blockIdx.x * blockDim.x + threadIdx.x;
    if (idx >= 512 * 256) return;
    int k = idx / 256, o = idx % 256;
    g_B2[idx] = (k < 256) ? W2l[o * 256 + k] : W2r[o * 256 + (k - 256)];
}

// ---------------- gather mean-aggregation + build concat A row ----------------
// one warp per destination node; F floats per row. A row = [mean_agg (F) | self (F)]
template <int F>
__global__ void agg_build_kernel(const float* __restrict__ X, float* __restrict__ A) {
    int warp = (blockIdx.x * blockDim.x + threadIdx.x) >> 5;
    int lane = threadIdx.x & 31;
    if (warp >= N_NODES) return;

    constexpr int V = F / 128;      // float4's per lane
    int s = g_off[warp];
    int e = g_off[warp + 1];

    float4 acc[V];
    #pragma unroll
    for (int v = 0; v < V; v++) acc[v] = make_float4(0.f, 0.f, 0.f, 0.f);

    for (int i = s; i < e; i++) {
        int src = __ldg(&g_csr[i]);
        const float4* xr = (const float4*)(X + (size_t)src * F);
        #pragma unroll
        for (int v = 0; v < V; v++) {
            float4 t = __ldg(&xr[lane + 32 * v]);
            acc[v].x += t.x; acc[v].y += t.y; acc[v].z += t.z; acc[v].w += t.w;
        }
    }

    float inv = (e > s) ? 1.f / (float)(e - s) : 0.f;
    float4* Ar = (float4*)(A + (size_t)warp * (2 * F));
    const float4* self = (const float4*)(X + (size_t)warp * F);
    #pragma unroll
    for (int v = 0; v < V; v++) {
        float4 o;
        o.x = acc[v].x * inv; o.y = acc[v].y * inv;
        o.z = acc[v].z * inv; o.w = acc[v].w * inv;
        Ar[lane + 32 * v] = o;
        Ar[F / 4 + lane + 32 * v] = __ldg(&self[lane + 32 * v]);
    }
}

// ---------------- SGEMM:  C[M,256] = A[M,K] @ B[K,256] + bias (optional relu) ----------------
#define BM 128
#define BN 64
#define BK 16
#define TM 8
#define TN 4
template <bool RELU>
__global__ void __launch_bounds__(256)
sgemm_bias_kernel(const float* __restrict__ A, const float* __restrict__ B,
                  const float* __restrict__ bias, float* __restrict__ C,
                  int M, int K) {
    __shared__ float As[BK][BM];
    __shared__ float Bs[BK][BN];

    const int NCOL = 256;
    int block_row = blockIdx.y * BM;
    int block_col = blockIdx.x * BN;
    int tid = threadIdx.x;
    int ty = tid >> 4;          // 0..15 -> row group of TM
    int tx = tid & 15;          // 0..15 -> col group of TN

    // A-tile loader coords: 2 x float4 per thread along K
    int aRow = tid >> 2;        // 0..63
    int aK   = (tid & 3) * 4;   // 0,4,8,12
    // B-tile loader coords: 1 x float4 per thread
    int bK   = tid >> 4;        // 0..15
    int bCol = (tid & 15) * 4;  // 0..60

    float acc[TM][TN];
    #pragma unroll
    for (int i = 0; i < TM; i++)
        #pragma unroll
        for (int j = 0; j < TN; j++) acc[i][j] = 0.f;

    for (int k0 = 0; k0 < K; k0 += BK) {
        #pragma unroll
        for (int r = 0; r < 2; r++) {
            int row = block_row + aRow + r * 64;
            float4 v = make_float4(0.f, 0.f, 0.f, 0.f);
            if (row < M) v = *(const float4*)(A + (size_t)row * K + k0 + aK);
            As[aK + 0][aRow + r * 64] = v.x;
            As[aK + 1][aRow + r * 64] = v.y;
            As[aK + 2][aRow + r * 64] = v.z;
            As[aK + 3][aRow + r * 64] = v.w;
        }
        float4 bv = *(const float4*)(B + (size_t)(k0 + bK) * NCOL + block_col + bCol);
        *(float4*)&Bs[bK][bCol] = bv;
        __syncthreads();

        #pragma unroll
        for (int k = 0; k < BK; k++) {
            float a[TM], b[TN];
            #pragma unroll
            for (int i = 0; i < TM; i++) a[i] = As[k][ty * TM + i];
            #pragma unroll
            for (int j = 0; j < TN; j++) b[j] = Bs[k][tx * TN + j];
            #pragma unroll
            for (int i = 0; i < TM; i++)
                #pragma unroll
                for (int j = 0; j < TN; j++) acc[i][j] += a[i] * b[j];
        }
        __syncthreads();
    }

    int colbase = block_col + tx * TN;
    float4 bvec = *(const float4*)(bias + colbase);
    float bb[TN] = {bvec.x, bvec.y, bvec.z, bvec.w};
    #pragma unroll
    for (int i = 0; i < TM; i++) {
        int row = block_row + ty * TM + i;
        if (row >= M) continue;
        float4 o;
        float v0 = acc[i][0] + bb[0];
        float v1 = acc[i][1] + bb[1];
        float v2 = acc[i][2] + bb[2];
        float v3 = acc[i][3] + bb[3];
        if (RELU) {
            v0 = fmaxf(v0, 0.f); v1 = fmaxf(v1, 0.f);
            v2 = fmaxf(v2, 0.f); v3 = fmaxf(v3, 0.f);
        }
        o.x = v0; o.y = v1; o.z = v2; o.w = v3;
        *(float4*)(C + (size_t)row * NCOL + colbase) = o;
    }
}

// ---------------- heads: out1 = h@Wh1^T+bh1 (4), out2 = h@Wh2^T+bh2 (3) ----------------
__global__ void heads_kernel(const float* __restrict__ H,
                             const float* __restrict__ Wh1, const float* __restrict__ bh1,
                             const float* __restrict__ Wh2, const float* __restrict__ bh2,
                             float* __restrict__ out1, float* __restrict__ out2) {
    int warp = (blockIdx.x * blockDim.x + threadIdx.x) >> 5;
    int lane = threadIdx.x & 31;
    if (warp >= N_NODES) return;
    const float* h = H + (size_t)warp * 256;
    float hv[8];
    #pragma unroll
    for (int j = 0; j < 8; j++) hv[j] = __ldg(&h[lane + 32 * j]);

    #pragma unroll
    for (int o = 0; o < 4; o++) {
        const float* w = Wh1 + o * 256;
        float p = 0.f;
        #pragma unroll
        for (int j = 0; j < 8; j++) p += hv[j] * __ldg(&w[lane + 32 * j]);
        #pragma unroll
        for (int sft = 16; sft > 0; sft >>= 1) p += __shfl_xor_sync(0xffffffffu, p, sft);
        if (lane == 0) out1[warp * 4 + o] = p + bh1[o];
    }
    #pragma unroll
    for (int o = 0; o < 3; o++) {
        const float* w = Wh2 + o * 256;
        float p = 0.f;
        #pragma unroll
        for (int j = 0; j < 8; j++) p += hv[j] * __ldg(&w[lane + 32 * j]);
        #pragma unroll
        for (int sft = 16; sft > 0; sft >>= 1) p += __shfl_xor_sync(0xffffffffu, p, sft);
        if (lane == 0) out2[warp * 3 + o] = p + bh2[o];
    }
}

// ---------------- launch ----------------
extern "C" void kernel_launch(void* const* d_in, const int* in_sizes, int n_in,
                              void* d_out, int out_size) {
    const float* x   = (const float*)d_in[0];
    const int*   ei  = (const int*)d_in[1];
    const float* W1l = (const float*)d_in[2];
    const float* b1l = (const float*)d_in[3];
    const float* W1r = (const float*)d_in[4];
    const float* W2l = (const float*)d_in[5];
    const float* b2l = (const float*)d_in[6];
    const float* W2r = (const float*)d_in[7];
    const float* Wh1 = (const float*)d_in[8];
    const float* bh1 = (const float*)d_in[9];
    const float* Wh2 = (const float*)d_in[10];
    const float* bh2 = (const float*)d_in[11];

    const int* src = ei;
    const int* dst = ei + N_EDGES;

    float* out1 = (float*)d_out;                          // [N,4]
    float* out2 = (float*)d_out + (size_t)N_NODES * 4;    // [N,3]
    float* hbuf = (float*)d_out + (size_t)N_NODES * 7;    // [N,256]

    // scratch pointers via symbol lookup (no allocation)
    float *pA1, *pA2, *pH1, *pB1, *pB2;
    cudaGetSymbolAddress((void**)&pA1, g_A1);
    cudaGetSymbolAddress((void**)&pA2, g_A2);
    cudaGetSymbolAddress((void**)&pH1, g_h1);
    cudaGetSymbolAddress((void**)&pB1, g_B1);
    cudaGetSymbolAddress((void**)&pB2, g_B2);

    // --- CSR build (shared by both layers) ---
    zero_deg_kernel<<<(N_NODES + 255) / 256, 256>>>();
    count_kernel<<<(N_EDGES + 255) / 256, 256>>>(dst);
    scan_kernel<<<1, 1024>>>();
    fill_kernel<<<(N_EDGES + 255) / 256, 256>>>(src, dst);

    // --- weight packing ---
    pack1_kernel<<<(256 * 256 + 255) / 256, 256>>>(W1l, W1r);
    pack2_kernel<<<(512 * 256 + 255) / 256, 256>>>(W2l, W2r);

    int aggBlocks = (N_NODES * 32 + 255) / 256;

    // --- layer 1 ---
    agg_build_kernel<128><<<aggBlocks, 256>>>(x, pA1);
    {
        dim3 grid(256 / BN, (N_NODES + BM - 1) / BM);
        sgemm_bias_kernel<true><<<grid, 256>>>(pA1, pB1, b1l, pH1, N_NODES, 256);
    }

    // --- layer 2 ---
    agg_build_kernel<256><<<aggBlocks, 256>>>(pH1, pA2);
    {
        dim3 grid(256 / BN, (N_NODES + BM - 1) / BM);
        sgemm_bias_kernel<false><<<grid, 256>>>(pA2, pB2, b2l, hbuf, N_NODES, 512);
    }

    // --- heads ---
    heads_kernel<<<aggBlocks, 256>>>(hbuf, Wh1, bh1, Wh2, bh2, out1, out2);
}

// round 5
// speedup vs baseline: 1.8263x; 1.8263x over previous
#include <cuda_runtime.h>
#include <cstdio>

#define N_NODES 50000
#define N_EDGES 800000
#define F_IN    128
#define HID     256

// ---------------- device scratch (static allocation only) ----------------
__device__ int   g_deg[N_NODES];
__device__ int   g_off[N_NODES + 1];
__device__ int   g_cur[N_NODES];
__device__ int   g_csr[N_EDGES];
__device__ float g_A1[(size_t)N_NODES * 256];   // [agg1_mean | x]        K=256
__device__ float g_h1[(size_t)N_NODES * 256];   // relu(layer1)
__device__ float g_A2[(size_t)N_NODES * 512];   // [agg2_mean | h1]       K=512
__device__ float g_B1[256 * 256];               // packed [K=256, O=256]
__device__ float g_B2[512 * 256];               // packed [K=512, O=256]

// ---------------- CSR build ----------------
__global__ void zero_deg_kernel() {
    int i = blockIdx.x * blockDim.x + threadIdx.x;
    if (i < N_NODES) g_deg[i] = 0;
}

__global__ void count_kernel(const int* __restrict__ dst) {
    int e = blockIdx.x * blockDim.x + threadIdx.x;
    if (e < N_EDGES) atomicAdd(&g_deg[dst[e]], 1);
}

// single-block hierarchical scan over degrees -> exclusive offsets (+ cursor copy)
__global__ void scan_kernel() {
    __shared__ int s[1024];
    int tid = threadIdx.x;
    int carry = 0;
    for (int base = 0; base < N_NODES; base += 1024) {
        int i = base + tid;
        int v = (i < N_NODES) ? g_deg[i] : 0;
        s[tid] = v;
        __syncthreads();
        #pragma unroll
        for (int off = 1; off < 1024; off <<= 1) {
            int t = (tid >= off) ? s[tid - off] : 0;
            __syncthreads();
            s[tid] += t;
            __syncthreads();
        }
        if (i < N_NODES) {
            int excl = carry + s[tid] - v;
            g_off[i] = excl;
            g_cur[i] = excl;
        }
        carry += s[1023];
        __syncthreads();
    }
    if (tid == 0) g_off[N_NODES] = carry;
}

__global__ void fill_kernel(const int* __restrict__ src, const int* __restrict__ dst) {
    int e = blockIdx.x * blockDim.x + threadIdx.x;
    if (e < N_EDGES) {
        int d = dst[e];
        int p = atomicAdd(&g_cur[d], 1);
        g_csr[p] = src[e];
    }
}

// ---------------- weight packing:  B[k][o] layout, concat of (Wl | Wr) along K ----------------
__global__ void pack1_kernel(const float* __restrict__ W1l, const float* __restrict__ W1r) {
    int idx = blockIdx.x * blockDim.x + threadIdx.x;
    if (idx >= 256 * 256) return;
    int k = idx / 256, o = idx % 256;
    g_B1[idx] = (k < 128) ? W1l[o * 128 + k] : W1r[o * 128 + (k - 128)];
}

__global__ void pack2_kernel(const float* __restrict__ W2l, const float* __restrict__ W2r) {
    int idx = blockIdx.x * blockDim.x + threadIdx.x;
    if (idx >= 512 * 256) return;
    int k = idx / 256, o = idx % 256;
    g_B2[idx] = (k < 256) ? W2l[o * 256 + k] : W2r[o * 256 + (k - 256)];
}

// ---------------- gather mean-aggregation + build concat A row ----------------
template <int F>
__global__ void agg_build_kernel(const float* __restrict__ X, float* __restrict__ A) {
    int warp = (blockIdx.x * blockDim.x + threadIdx.x) >> 5;
    int lane = threadIdx.x & 31;
    if (warp >= N_NODES) return;

    constexpr int V = F / 128;      // float4's per lane
    int s = g_off[warp];
    int e = g_off[warp + 1];

    float4 acc[V];
    #pragma unroll
    for (int v = 0; v < V; v++) acc[v] = make_float4(0.f, 0.f, 0.f, 0.f);

    for (int i = s; i < e; i++) {
        int src = __ldg(&g_csr[i]);
        const float4* xr = (const float4*)(X + (size_t)src * F);
        #pragma unroll
        for (int v = 0; v < V; v++) {
            float4 t = __ldg(&xr[lane + 32 * v]);
            acc[v].x += t.x; acc[v].y += t.y; acc[v].z += t.z; acc[v].w += t.w;
        }
    }

    float inv = (e > s) ? 1.f / (float)(e - s) : 0.f;
    float4* Ar = (float4*)(A + (size_t)warp * (2 * F));
    const float4* self = (const float4*)(X + (size_t)warp * F);
    #pragma unroll
    for (int v = 0; v < V; v++) {
        float4 o;
        o.x = acc[v].x * inv; o.y = acc[v].y * inv;
        o.z = acc[v].z * inv; o.w = acc[v].w * inv;
        Ar[lane + 32 * v] = o;
        Ar[F / 4 + lane + 32 * v] = __ldg(&self[lane + 32 * v]);
    }
}

// ---------------- TF32 tensor-core GEMM ----------------
// C[M,256] = A[M,K] @ B[K,256] + bias (optional relu)
// block tile 128x128, 8 warps (4 along M x 2 along N), warp tile 32x64,
// mma.sync m16n8k8 tf32, BK=16 with register prefetch.

__device__ __forceinline__ float to_tf32(float x) {
    float r;
    asm("cvt.rna.tf32.f32 %0, %1;" : "=f"(r) : "f"(x));
    return r;
}

__device__ __forceinline__ float4 tf32x4(float4 v) {
    return make_float4(to_tf32(v.x), to_tf32(v.y), to_tf32(v.z), to_tf32(v.w));
}

__device__ __forceinline__ void mma_tf32(float* d, const unsigned* a, const unsigned* b) {
    asm volatile(
        "mma.sync.aligned.m16n8k8.row.col.f32.tf32.tf32.f32 "
        "{%0,%1,%2,%3}, {%4,%5,%6,%7}, {%8,%9}, {%0,%1,%2,%3};\n"
        : "+f"(d[0]), "+f"(d[1]), "+f"(d[2]), "+f"(d[3])
        : "r"(a[0]), "r"(a[1]), "r"(a[2]), "r"(a[3]), "r"(b[0]), "r"(b[1]));
}

template <bool RELU>
__global__ void __launch_bounds__(256)
tf32_gemm_bias_kernel(const float* __restrict__ A, const float* __restrict__ B,
                      const float* __restrict__ bias, float* __restrict__ C,
                      int M, int K) {
    const int NCOL = 256;
    __shared__ float As[128][20];    // [m][k], pad to 20 -> conflict-free frag LDS
    __shared__ float Bs[16][136];    // [k][n], pad to 136 -> conflict-free frag LDS

    int tid  = threadIdx.x;
    int lane = tid & 31;
    int wid  = tid >> 5;
    int warp_m = (wid & 3) * 32;
    int warp_n = (wid >> 2) * 64;
    int block_row = blockIdx.y * 128;
    int block_col = blockIdx.x * 128;

    // global->smem loader coords
    int aRow = tid >> 2;            // 0..63 (plus +64 for second half)
    int aK   = (tid & 3) * 4;       // 0,4,8,12
    int bK   = tid >> 4;            // 0..15
    int bCol = (tid & 15) * 4;      // 0..60 (plus +64)

    bool aV0 = (block_row + aRow) < M;
    bool aV1 = (block_row + aRow + 64) < M;
    const float* Ap0 = A + (size_t)(block_row + aRow) * K + aK;
    const float* Ap1 = A + (size_t)(block_row + aRow + 64) * K + aK;
    const float* Bp  = B + (size_t)bK * NCOL + block_col + bCol;

    float acc[2][8][4];
    #pragma unroll
    for (int mt = 0; mt < 2; mt++)
        #pragma unroll
        for (int nt = 0; nt < 8; nt++)
            #pragma unroll
            for (int c = 0; c < 4; c++) acc[mt][nt][c] = 0.f;

    const float4 z4 = make_float4(0.f, 0.f, 0.f, 0.f);

    // initial tile load
    {
        float4 rA0 = aV0 ? *(const float4*)Ap0 : z4;
        float4 rA1 = aV1 ? *(const float4*)Ap1 : z4;
        float4 rB0 = *(const float4*)Bp;
        float4 rB1 = *(const float4*)(Bp + 64);
        *(float4*)&As[aRow][aK]        = tf32x4(rA0);
        *(float4*)&As[aRow + 64][aK]   = tf32x4(rA1);
        *(float4*)&Bs[bK][bCol]        = tf32x4(rB0);
        *(float4*)&Bs[bK][bCol + 64]   = tf32x4(rB1);
    }
    __syncthreads();

    for (int k0 = 0; k0 < K; k0 += 16) {
        bool has_next = (k0 + 16) < K;
        float4 nA0 = z4, nA1 = z4, nB0 = z4, nB1 = z4;
        if (has_next) {
            if (aV0) nA0 = *(const float4*)(Ap0 + k0 + 16);
            if (aV1) nA1 = *(const float4*)(Ap1 + k0 + 16);
            nB0 = *(const float4*)(Bp + (size_t)(k0 + 16) * NCOL);
            nB1 = *(const float4*)(Bp + (size_t)(k0 + 16) * NCOL + 64);
        }

        // compute on current smem tile (two k=8 sub-steps)
        #pragma unroll
        for (int kk = 0; kk < 16; kk += 8) {
            unsigned afr[2][4];
            #pragma unroll
            for (int mt = 0; mt < 2; mt++) {
                int mr = warp_m + mt * 16 + (lane >> 2);
                int kc = kk + (lane & 3);
                afr[mt][0] = __float_as_uint(As[mr][kc]);
                afr[mt][1] = __float_as_uint(As[mr + 8][kc]);
                afr[mt][2] = __float_as_uint(As[mr][kc + 4]);
                afr[mt][3] = __float_as_uint(As[mr + 8][kc + 4]);
            }
            unsigned bfr[8][2];
            #pragma unroll
            for (int nt = 0; nt < 8; nt++) {
                int nc = warp_n + nt * 8 + (lane >> 2);
                int kr = kk + (lane & 3);
                bfr[nt][0] = __float_as_uint(Bs[kr][nc]);
                bfr[nt][1] = __float_as_uint(Bs[kr + 4][nc]);
            }
            #pragma unroll
            for (int mt = 0; mt < 2; mt++)
                #pragma unroll
                for (int nt = 0; nt < 8; nt++)
                    mma_tf32(acc[mt][nt], afr[mt], bfr[nt]);
        }
        __syncthreads();

        if (has_next) {
            *(float4*)&As[aRow][aK]      = tf32x4(nA0);
            *(float4*)&As[aRow + 64][aK] = tf32x4(nA1);
            *(float4*)&Bs[bK][bCol]      = tf32x4(nB0);
            *(float4*)&Bs[bK][bCol + 64] = tf32x4(nB1);
        }
        __syncthreads();
    }

    // epilogue: bias (+relu), float2 stores
    #pragma unroll
    for (int nt = 0; nt < 8; nt++) {
        int col = block_col + warp_n + nt * 8 + (lane & 3) * 2;
        float b0 = __ldg(&bias[col]);
        float b1 = __ldg(&bias[col + 1]);
        #pragma unroll
        for (int mt = 0; mt < 2; mt++) {
            int row0 = block_row + warp_m + mt * 16 + (lane >> 2);
            float v0 = acc[mt][nt][0] + b0;
            float v1 = acc[mt][nt][1] + b1;
            float v2 = acc[mt][nt][2] + b0;
            float v3 = acc[mt][nt][3] + b1;
            if (RELU) {
                v0 = fmaxf(v0, 0.f); v1 = fmaxf(v1, 0.f);
                v2 = fmaxf(v2, 0.f); v3 = fmaxf(v3, 0.f);
            }
            if (row0 < M)
                *(float2*)(C + (size_t)row0 * NCOL + col) = make_float2(v0, v1);
            if (row0 + 8 < M)
                *(float2*)(C + (size_t)(row0 + 8) * NCOL + col) = make_float2(v2, v3);
        }
    }
}

// ---------------- heads: out1 = h@Wh1^T+bh1 (4), out2 = h@Wh2^T+bh2 (3) ----------------
__global__ void heads_kernel(const float* __restrict__ H,
                             const float* __restrict__ Wh1, const float* __restrict__ bh1,
                             const float* __restrict__ Wh2, const float* __restrict__ bh2,
                             float* __restrict__ out1, float* __restrict__ out2) {
    int warp = (blockIdx.x * blockDim.x + threadIdx.x) >> 5;
    int lane = threadIdx.x & 31;
    if (warp >= N_NODES) return;
    const float* h = H + (size_t)warp * 256;
    float hv[8];
    #pragma unroll
    for (int j = 0; j < 8; j++) hv[j] = __ldg(&h[lane + 32 * j]);

    #pragma unroll
    for (int o = 0; o < 4; o++) {
        const float* w = Wh1 + o * 256;
        float p = 0.f;
        #pragma unroll
        for (int j = 0; j < 8; j++) p += hv[j] * __ldg(&w[lane + 32 * j]);
        #pragma unroll
        for (int sft = 16; sft > 0; sft >>= 1) p += __shfl_xor_sync(0xffffffffu, p, sft);
        if (lane == 0) out1[warp * 4 + o] = p + bh1[o];
    }
    #pragma unroll
    for (int o = 0; o < 3; o++) {
        const float* w = Wh2 + o * 256;
        float p = 0.f;
        #pragma unroll
        for (int j = 0; j < 8; j++) p += hv[j] * __ldg(&w[lane + 32 * j]);
        #pragma unroll
        for (int sft = 16; sft > 0; sft >>= 1) p += __shfl_xor_sync(0xffffffffu, p, sft);
        if (lane == 0) out2[warp * 3 + o] = p + bh2[o];
    }
}

// ---------------- launch ----------------
extern "C" void kernel_launch(void* const* d_in, const int* in_sizes, int n_in,
                              void* d_out, int out_size) {
    const float* x   = (const float*)d_in[0];
    const int*   ei  = (const int*)d_in[1];
    const float* W1l = (const float*)d_in[2];
    const float* b1l = (const float*)d_in[3];
    const float* W1r = (const float*)d_in[4];
    const float* W2l = (const float*)d_in[5];
    const float* b2l = (const float*)d_in[6];
    const float* W2r = (const float*)d_in[7];
    const float* Wh1 = (const float*)d_in[8];
    const float* bh1 = (const float*)d_in[9];
    const float* Wh2 = (const float*)d_in[10];
    const float* bh2 = (const float*)d_in[11];

    const int* src = ei;
    const int* dst = ei + N_EDGES;

    float* out1 = (float*)d_out;                          // [N,4]
    float* out2 = (float*)d_out + (size_t)N_NODES * 4;    // [N,3]
    float* hbuf = (float*)d_out + (size_t)N_NODES * 7;    // [N,256]

    // scratch pointers via symbol lookup (no allocation)
    float *pA1, *pA2, *pH1, *pB1, *pB2;
    cudaGetSymbolAddress((void**)&pA1, g_A1);
    cudaGetSymbolAddress((void**)&pA2, g_A2);
    cudaGetSymbolAddress((void**)&pH1, g_h1);
    cudaGetSymbolAddress((void**)&pB1, g_B1);
    cudaGetSymbolAddress((void**)&pB2, g_B2);

    // --- CSR build (shared by both layers) ---
    zero_deg_kernel<<<(N_NODES + 255) / 256, 256>>>();
    count_kernel<<<(N_EDGES + 255) / 256, 256>>>(dst);
    scan_kernel<<<1, 1024>>>();
    fill_kernel<<<(N_EDGES + 255) / 256, 256>>>(src, dst);

    // --- weight packing ---
    pack1_kernel<<<(256 * 256 + 255) / 256, 256>>>(W1l, W1r);
    pack2_kernel<<<(512 * 256 + 255) / 256, 256>>>(W2l, W2r);

    int aggBlocks = (N_NODES * 32 + 255) / 256;

    // --- layer 1 ---
    agg_build_kernel<128><<<aggBlocks, 256>>>(x, pA1);
    {
        dim3 grid(2, (N_NODES + 127) / 128);
        tf32_gemm_bias_kernel<true><<<grid, 256>>>(pA1, pB1, b1l, pH1, N_NODES, 256);
    }

    // --- layer 2 ---
    agg_build_kernel<256><<<aggBlocks, 256>>>(pH1, pA2);
    {
        dim3 grid(2, (N_NODES + 127) / 128);
        tf32_gemm_bias_kernel<false><<<grid, 256>>>(pA2, pB2, b2l, hbuf, N_NODES, 512);
    }

    // --- heads ---
    heads_kernel<<<aggBlocks, 256>>>(hbuf, Wh1, bh1, Wh2, bh2, out1, out2);
}